// round 2
// baseline (speedup 1.0000x reference)
#include <cuda_runtime.h>
#include <cstdint>

// ---------------- problem constants ----------------
#define B_  8
#define C_  64
#define O_  64
#define H_  128
#define W_  128
#define K2_ 9
#define HW_ (H_*W_)          // 16384
#define J_  (C_*K2_)         // 576
#define PX_ 16               // pixels per block in kernel C
#define SVST_ 577            // padded row stride for sv (577 % 32 == 1)

// ---------------- scratch (device globals; no allocation allowed) ----------
__device__ __align__(16) float g_xt[B_*HW_*C_];      // NHWC transpose of x (33.5 MB)
__device__ __align__(16) float g_offm[B_*HW_*27];    // per pixel, per k: {dy, dx, mask}
__device__ __align__(16) float g_wt[J_*O_];          // Wt[j][o], j = c*9+k (147 KB)

// ---------------- f32x2 helpers ----------------
__device__ __forceinline__ void fma2(unsigned long long &d, unsigned long long a, unsigned long long b) {
    asm("fma.rn.f32x2 %0, %1, %2, %0;" : "+l"(d) : "l"(a), "l"(b));
}
__device__ __forceinline__ unsigned long long pack2(float x, float y) {
    unsigned long long r;
    asm("mov.b64 %0, {%1, %2};" : "=l"(r) : "f"(x), "f"(y));
    return r;
}
__device__ __forceinline__ float2 unpack2(unsigned long long v) {
    float2 r;
    asm("mov.b64 {%0, %1}, %2;" : "=f"(r.x), "=f"(r.y) : "l"(v));
    return r;
}

// ---------------- kernel A: NCHW -> NHWC transpose of x ----------------
// grid (HW/32, C/32, B), block (32, 8)
__global__ void transpose_kernel(const float* __restrict__ x) {
    __shared__ float tile[32][33];
    int b  = blockIdx.z;
    int s0 = blockIdx.x * 32;   // spatial (h*W+w)
    int c0 = blockIdx.y * 32;   // channel
    #pragma unroll
    for (int i = threadIdx.y; i < 32; i += 8)
        tile[i][threadIdx.x] = x[(size_t)(b*C_ + c0 + i) * HW_ + s0 + threadIdx.x];
    __syncthreads();
    #pragma unroll
    for (int i = threadIdx.y; i < 32; i += 8)
        g_xt[(size_t)(b*HW_ + s0 + i) * C_ + c0 + threadIdx.x] = tile[threadIdx.x][i];
}

// ---------------- kernel A2: transpose w (O,C,3,3) -> Wt[j][o] ----------------
__global__ void wt_kernel(const float* __restrict__ w) {
    int idx = blockIdx.x * blockDim.x + threadIdx.x;
    if (idx < J_*O_) {
        int o = idx & 63;
        int j = idx >> 6;
        g_wt[idx] = w[o * J_ + j];
    }
}

// ---------------- kernel B: offset + mask 3x3 conv (27 channels) ----------------
// block = 128 threads (one w-row), grid (H, B). Reads x in NCHW (coalesced).
// Accumulates 28 (padded) outputs as 14 f32x2 pairs. Weights staged in smem
// per 32-channel half: ws[c][t][28], broadcast LDS.
__global__ void conv_kernel(const float* __restrict__ x,
                            const float* __restrict__ w_off,
                            const float* __restrict__ b_off,
                            const float* __restrict__ w_mod,
                            const float* __restrict__ b_mod) {
    __shared__ float ws[32*9*28];   // 32 KB
    const int w = threadIdx.x;
    const int h = blockIdx.x;
    const int b = blockIdx.y;

    unsigned long long acc[14];
    #pragma unroll
    for (int j = 0; j < 14; ++j) acc[j] = 0ull;

    for (int half = 0; half < 2; ++half) {
        __syncthreads();
        // stage weights for channels [half*32, half*32+32)
        for (int idx = threadIdx.x; idx < 32*9*28; idx += 128) {
            int j = idx % 28;
            int t = (idx / 28) % 9;
            int c = idx / (28*9) + half*32;
            float v = 0.f;
            if (j < 18)      v = w_off[((j*C_ + c) * 9) + t];
            else if (j < 27) v = w_mod[(((j-18)*C_ + c) * 9) + t];
            ws[idx] = v;
        }
        __syncthreads();

        const float* xb = x + (size_t)(b*C_ + half*32) * HW_;
        for (int c = 0; c < 32; ++c) {
            const float* xc = xb + (size_t)c * HW_;
            #pragma unroll
            for (int t = 0; t < 9; ++t) {
                int yy = h + t/3 - 1;
                int xx = w + t%3 - 1;
                float xv = 0.f;
                if (yy >= 0 && yy < H_ && xx >= 0 && xx < W_)
                    xv = xc[yy*W_ + xx];
                unsigned long long xv2 = pack2(xv, xv);
                const unsigned long long* wp =
                    (const unsigned long long*)&ws[(c*9 + t) * 28];
                #pragma unroll
                for (int j = 0; j < 14; ++j) fma2(acc[j], xv2, wp[j]);
            }
        }
    }

    float ov[28];
    #pragma unroll
    for (int j = 0; j < 14; ++j) {
        float2 f = unpack2(acc[j]);
        ov[2*j] = f.x; ov[2*j+1] = f.y;
    }
    float* om = g_offm + ((size_t)(b*HW_ + h*W_ + w) * 27);
    #pragma unroll
    for (int k = 0; k < 9; ++k) {
        om[k*3 + 0] = ov[2*k]     + b_off[2*k];
        om[k*3 + 1] = ov[2*k + 1] + b_off[2*k + 1];
        float z = ov[18 + k] + b_mod[k];
        om[k*3 + 2] = 2.f / (1.f + expf(-z));
    }
}

// ---------------- kernel C: bilinear sampling + per-pixel GEMM ----------------
// block = 256 threads, 16 pixels (one b, one h, 16 consecutive w).
// Phase 1: 144 warp-tasks (pixel,k) build sv[p][c*9+k] = sampled*mask in smem.
// Phase 2: thread (p, og) computes out[p][og*4 .. og*4+3] with f32x2 FMAs.
__global__ void sample_gemm_kernel(const float* __restrict__ bias,
                                   float* __restrict__ out) {
    __shared__ float sv[PX_ * SVST_];   // 36928 B (static, <48KB)
    const int tid  = threadIdx.x;
    const int lane = tid & 31;
    const int wid  = tid >> 5;
    const int b  = blockIdx.z;
    const int h  = blockIdx.y;
    const int w0 = blockIdx.x * PX_;

    // ---- phase 1: sampling (144 tasks = 16 px * 9 taps, over 8 warps) ----
    const float* xtb = g_xt + (size_t)b * HW_ * C_;
    for (int task = wid; task < PX_*9; task += 8) {
        int p = task & (PX_-1);
        int k = task / PX_;
        int w = w0 + p;
        const float* om = g_offm + ((size_t)(b*HW_ + h*W_ + w) * 27) + k*3;
        float dy = om[0], dx = om[1], m = om[2];
        float py = dy + (float)(h - 1 + k/3);
        float px = dx + (float)(w - 1 + k%3);
        float y0f = floorf(py), x0f = floorf(px);
        float wy = py - y0f,    wx = px - x0f;
        int y0 = (int)y0f, x0 = (int)x0f;
        float w00 = (1.f-wy)*(1.f-wx), w01 = (1.f-wy)*wx;
        float w10 = wy*(1.f-wx),       w11 = wy*wx;
        bool vy0 = (y0   >= 0) && (y0   < H_);
        bool vy1 = (y0+1 >= 0) && (y0+1 < H_);
        bool vx0 = (x0   >= 0) && (x0   < W_);
        bool vx1 = (x0+1 >= 0) && (x0+1 < W_);
        int r00 = (y0*W_ + x0) * C_;
        int r01 = r00 + C_;
        int r10 = r00 + W_*C_;
        int r11 = r10 + C_;
        #pragma unroll
        for (int cc = 0; cc < 2; ++cc) {
            int c = lane + cc*32;
            float v00 = (vy0 && vx0) ? xtb[r00 + c] : 0.f;
            float v01 = (vy0 && vx1) ? xtb[r01 + c] : 0.f;
            float v10 = (vy1 && vx0) ? xtb[r10 + c] : 0.f;
            float v11 = (vy1 && vx1) ? xtb[r11 + c] : 0.f;
            float s = v00*w00 + v01*w01 + v10*w10 + v11*w11;
            sv[p*SVST_ + c*9 + k] = s * m;
        }
    }
    __syncthreads();

    // ---- phase 2: GEMM out[p][o] = sum_j Wt[j][o] * v[p][j] ----
    // 256 threads = 16 pixels * 16 o-groups; 4 outputs per thread.
    const int p  = tid >> 4;          // 0..15
    const int og = tid & 15;          // 0..15 -> o = og*4 .. og*4+3
    const float* svp = sv + p*SVST_;
    unsigned long long a0 = 0ull, a1 = 0ull;
    #pragma unroll 8
    for (int j = 0; j < J_; ++j) {
        float vv = svp[j];
        unsigned long long vv2 = pack2(vv, vv);
        const ulonglong2* wq = (const ulonglong2*)(g_wt + j*O_ + og*4);
        ulonglong2 q = *wq;
        fma2(a0, vv2, q.x);
        fma2(a1, vv2, q.y);
    }
    float2 f0 = unpack2(a0), f1 = unpack2(a1);
    int o0 = og * 4;
    float* op = out + ((size_t)(b*O_ + o0) * HW_ + h*W_ + w0 + p);
    const float* bp = bias + o0;
    op[0*HW_] = f0.x + bp[0];
    op[1*HW_] = f0.y + bp[1];
    op[2*HW_] = f1.x + bp[2];
    op[3*HW_] = f1.y + bp[3];
}

// ---------------- launch ----------------
extern "C" void kernel_launch(void* const* d_in, const int* in_sizes, int n_in,
                              void* d_out, int out_size) {
    (void)in_sizes; (void)n_in; (void)out_size;
    const float* x     = (const float*)d_in[0];
    const float* w_off = (const float*)d_in[1];
    const float* b_off = (const float*)d_in[2];
    const float* w_mod = (const float*)d_in[3];
    const float* b_mod = (const float*)d_in[4];
    const float* w     = (const float*)d_in[5];
    const float* bias  = (const float*)d_in[6];
    float* out = (float*)d_out;

    transpose_kernel<<<dim3(HW_/32, C_/32, B_), dim3(32, 8)>>>(x);
    wt_kernel<<<(J_*O_ + 255)/256, 256>>>(w);
    conv_kernel<<<dim3(H_, B_), 128>>>(x, w_off, b_off, w_mod, b_mod);
    sample_gemm_kernel<<<dim3(W_/PX_, H_, B_), 256>>>(bias, out);
}

// round 6
// speedup vs baseline: 2.2406x; 2.2406x over previous
#include <cuda_runtime.h>
#include <cstdint>

// ---------------- problem constants ----------------
#define B_  8
#define C_  64
#define O_  64
#define H_  128
#define W_  128
#define HW_ (H_*W_)          // 16384
#define J_  (C_*9)           // 576
#define ST_ 34               // sv row stride (floats): 2-way STS conflict, LDS.64-clean

// ---------------- scratch (device globals; no allocation allowed) ----------
__device__ __align__(16) float g_xt[B_*HW_*C_];      // NHWC transpose of x
__device__ __align__(16) float g_offm[B_*HW_*27];    // per pixel,k: {dy,dx,mask}
__device__ __align__(16) float g_wt[J_*O_];          // Wt[j][o]

// ---------------- f32x2 helpers ----------------
__device__ __forceinline__ void fma2(unsigned long long &d, unsigned long long a, unsigned long long b) {
    asm("fma.rn.f32x2 %0, %1, %2, %0;" : "+l"(d) : "l"(a), "l"(b));
}
__device__ __forceinline__ unsigned long long pack2(float x, float y) {
    unsigned long long r;
    asm("mov.b64 %0, {%1, %2};" : "=l"(r) : "f"(x), "f"(y));
    return r;
}
__device__ __forceinline__ float2 unpack2(unsigned long long v) {
    float2 r;
    asm("mov.b64 {%0, %1}, %2;" : "=f"(r.x), "=f"(r.y) : "l"(v));
    return r;
}

// ---------------- kernel A: NCHW -> NHWC transpose of x ----------------
__global__ void transpose_kernel(const float* __restrict__ x) {
    __shared__ float tile[32][33];
    int b  = blockIdx.z;
    int s0 = blockIdx.x * 32;
    int c0 = blockIdx.y * 32;
    #pragma unroll
    for (int i = threadIdx.y; i < 32; i += 8)
        tile[i][threadIdx.x] = x[(size_t)(b*C_ + c0 + i) * HW_ + s0 + threadIdx.x];
    __syncthreads();
    #pragma unroll
    for (int i = threadIdx.y; i < 32; i += 8)
        g_xt[(size_t)(b*HW_ + s0 + i) * C_ + c0 + threadIdx.x] = tile[threadIdx.x][i];
}

// ---------------- kernel A2: w (O,C,3,3) -> Wt[j][o] ----------------
__global__ void wt_kernel(const float* __restrict__ w) {
    int idx = blockIdx.x * blockDim.x + threadIdx.x;
    if (idx < J_*O_) {
        int o = idx & 63;
        int j = idx >> 6;
        g_wt[idx] = w[o * J_ + j];
    }
}

// ---------------- kernel B: offset + mask 3x3 conv (27 channels) ----------------
__global__ void conv_kernel(const float* __restrict__ x,
                            const float* __restrict__ w_off,
                            const float* __restrict__ b_off,
                            const float* __restrict__ w_mod,
                            const float* __restrict__ b_mod) {
    __shared__ float ws[32*9*28];
    const int w = threadIdx.x;
    const int h = blockIdx.x;
    const int b = blockIdx.y;

    unsigned long long acc[14];
    #pragma unroll
    for (int j = 0; j < 14; ++j) acc[j] = 0ull;

    for (int half = 0; half < 2; ++half) {
        __syncthreads();
        for (int idx = threadIdx.x; idx < 32*9*28; idx += 128) {
            int j = idx % 28;
            int t = (idx / 28) % 9;
            int c = idx / (28*9) + half*32;
            float v = 0.f;
            if (j < 18)      v = w_off[((j*C_ + c) * 9) + t];
            else if (j < 27) v = w_mod[(((j-18)*C_ + c) * 9) + t];
            ws[idx] = v;
        }
        __syncthreads();

        const float* xb = x + (size_t)(b*C_ + half*32) * HW_;
        for (int c = 0; c < 32; ++c) {
            const float* xc = xb + (size_t)c * HW_;
            #pragma unroll
            for (int t = 0; t < 9; ++t) {
                int yy = h + t/3 - 1;
                int xx = w + t%3 - 1;
                float xv = 0.f;
                if (yy >= 0 && yy < H_ && xx >= 0 && xx < W_)
                    xv = xc[yy*W_ + xx];
                unsigned long long xv2 = pack2(xv, xv);
                const unsigned long long* wp =
                    (const unsigned long long*)&ws[(c*9 + t) * 28];
                #pragma unroll
                for (int j = 0; j < 14; ++j) fma2(acc[j], xv2, wp[j]);
            }
        }
    }

    float ov[28];
    #pragma unroll
    for (int j = 0; j < 14; ++j) {
        float2 f = unpack2(acc[j]);
        ov[2*j] = f.x; ov[2*j+1] = f.y;
    }
    float* om = g_offm + ((size_t)(b*HW_ + h*W_ + w) * 27);
    #pragma unroll
    for (int k = 0; k < 9; ++k) {
        om[k*3 + 0] = ov[2*k]     + b_off[2*k];
        om[k*3 + 1] = ov[2*k + 1] + b_off[2*k + 1];
        float z = ov[18 + k] + b_mod[k];
        om[k*3 + 2] = 2.f / (1.f + expf(-z));
    }
}

// ---------------- kernel C: sampling + per-pixel GEMM (register-blocked) ----
// 256 threads, 32 pixels (one b,h; 32 consecutive w).
// Phase 0: precompute 288 task records (folded weights + clamped offsets).
// Chunk loop (2 x 32 channels):
//   Phase 1: gather+combine -> sv[j_local][pixel]  (j_local = c_local*9+k)
//   Phase 2: each thread: 2 pixels x 8 outputs, j-split across warp halves.
// Final: cross-half reduction through smem, add bias, store.
__global__ void __launch_bounds__(256, 4)
sample_gemm_kernel(const float* __restrict__ bias, float* __restrict__ out) {
    __shared__ float sv[288*ST_];    // 39168 B (also reused as reduction scratch)
    __shared__ float trw[288*4];     // folded weights
    __shared__ int   trr[288*4];     // clamped NHWC row offsets

    const int tid  = threadIdx.x;
    const int lane = tid & 31;
    const int wid  = tid >> 5;
    const int b  = blockIdx.z;
    const int h  = blockIdx.y;
    const int w0 = blockIdx.x * 32;

    // ---- phase 0: task records ----
    for (int t = tid; t < 288; t += 256) {
        int p = t & 31;
        int k = t >> 5;
        int w = w0 + p;
        const float* om = g_offm + ((size_t)(b*HW_ + h*W_ + w) * 27) + k*3;
        float dy = om[0], dx = om[1], m = om[2];
        float py = dy + (float)(h - 1 + k/3);
        float px = dx + (float)(w - 1 + k%3);
        float y0f = floorf(py), x0f = floorf(px);
        float wy = py - y0f,    wx = px - x0f;
        int y0 = (int)y0f, x0 = (int)x0f;
        int y1 = y0 + 1,   x1 = x0 + 1;
        float fy0 = (y0 >= 0 && y0 < H_) ? 1.f : 0.f;
        float fy1 = (y1 >= 0 && y1 < H_) ? 1.f : 0.f;
        float fx0 = (x0 >= 0 && x0 < W_) ? 1.f : 0.f;
        float fx1 = (x1 >= 0 && x1 < W_) ? 1.f : 0.f;
        int y0c = min(max(y0, 0), H_-1), y1c = min(max(y1, 0), H_-1);
        int x0c = min(max(x0, 0), W_-1), x1c = min(max(x1, 0), W_-1);
        trw[t*4+0] = (1.f-wy)*(1.f-wx) * m * fy0 * fx0;
        trw[t*4+1] = (1.f-wy)*wx       * m * fy0 * fx1;
        trw[t*4+2] = wy*(1.f-wx)       * m * fy1 * fx0;
        trw[t*4+3] = wy*wx             * m * fy1 * fx1;
        trr[t*4+0] = (y0c*W_ + x0c) * C_;
        trr[t*4+1] = (y0c*W_ + x1c) * C_;
        trr[t*4+2] = (y1c*W_ + x0c) * C_;
        trr[t*4+3] = (y1c*W_ + x1c) * C_;
    }

    // phase-2 thread mapping
    const int pg    = lane & 15;            // pixel pair -> pixels 2pg, 2pg+1
    const int oh    = lane >> 4;            // 0/1
    const int obase = (wid & 3)*16 + oh*8;  // 8 outputs
    const int jhalf = wid >> 2;             // j-split half

    unsigned long long aA0=0, aA1=0, aA2=0, aA3=0;   // pixel 2pg
    unsigned long long aB0=0, aB1=0, aB2=0, aB3=0;   // pixel 2pg+1

    const float* xtb = g_xt + (size_t)b * HW_ * C_;

    for (int ch = 0; ch < 2; ++ch) {
        __syncthreads();
        // ---- phase 1: gather (lane = channel within chunk) ----
        {
            const float* xc = xtb + ch*32 + lane;
            for (int t = wid; t < 288; t += 8) {
                float4 wv = *(const float4*)&trw[t*4];
                int4   rv = *(const int4*)&trr[t*4];
                float v00 = xc[rv.x];
                float v01 = xc[rv.y];
                float v10 = xc[rv.z];
                float v11 = xc[rv.w];
                float s = wv.x*v00 + wv.y*v01 + wv.z*v10 + wv.w*v11;
                int p = t & 31;
                int k = t >> 5;
                sv[(lane*9 + k)*ST_ + p] = s;
            }
        }
        __syncthreads();
        // ---- phase 2: partial GEMM over this chunk's 288 j's (144 per half) ----
        {
            const float* wt  = g_wt + (size_t)(ch*288 + jhalf*144) * 64 + obase;
            const float* svp = sv + (jhalf*144)*ST_ + 2*pg;
            #pragma unroll 4
            for (int jj = 0; jj < 144; ++jj) {
                float2 vv = *(const float2*)(svp + jj*ST_);
                const ulonglong2* wq = (const ulonglong2*)(wt + (size_t)jj*64);
                ulonglong2 qa = wq[0];
                ulonglong2 qb = wq[1];
                unsigned long long va = pack2(vv.x, vv.x);
                unsigned long long vb = pack2(vv.y, vv.y);
                fma2(aA0, va, qa.x); fma2(aA1, va, qa.y);
                fma2(aA2, va, qb.x); fma2(aA3, va, qb.y);
                fma2(aB0, vb, qa.x); fma2(aB1, vb, qa.y);
                fma2(aB2, vb, qb.x); fma2(aB3, vb, qb.y);
            }
        }
    }

    // ---- reduction across j-halves (reuse sv as scratch [32 px][stride 72]) ----
    __syncthreads();
    float* scr = sv;
    const int p0 = 2*pg;
    if (jhalf == 1) {
        *(float2*)&scr[ p0   *72 + obase + 0] = unpack2(aA0);
        *(float2*)&scr[ p0   *72 + obase + 2] = unpack2(aA1);
        *(float2*)&scr[ p0   *72 + obase + 4] = unpack2(aA2);
        *(float2*)&scr[ p0   *72 + obase + 6] = unpack2(aA3);
        *(float2*)&scr[(p0+1)*72 + obase + 0] = unpack2(aB0);
        *(float2*)&scr[(p0+1)*72 + obase + 2] = unpack2(aB1);
        *(float2*)&scr[(p0+1)*72 + obase + 4] = unpack2(aB2);
        *(float2*)&scr[(p0+1)*72 + obase + 6] = unpack2(aB3);
    }
    __syncthreads();
    if (jhalf == 0) {
        unsigned long long accs[8] = {aA0,aA1,aA2,aA3,aB0,aB1,aB2,aB3};
        #pragma unroll
        for (int i = 0; i < 8; ++i) {
            int pp = p0 + (i >> 2);
            int oo = obase + 2*(i & 3);
            float2 sA = *(float2*)&scr[pp*72 + oo];
            float2 a  = unpack2(accs[i]);
            float r0 = a.x + sA.x + bias[oo];
            float r1 = a.y + sA.y + bias[oo+1];
            size_t base = (size_t)b*O_*HW_ + (size_t)h*W_ + w0 + pp;
            out[base + (size_t)oo    *HW_] = r0;
            out[base + (size_t)(oo+1)*HW_] = r1;
        }
    }
}

// ---------------- launch ----------------
extern "C" void kernel_launch(void* const* d_in, const int* in_sizes, int n_in,
                              void* d_out, int out_size) {
    (void)in_sizes; (void)n_in; (void)out_size;
    const float* x     = (const float*)d_in[0];
    const float* w_off = (const float*)d_in[1];
    const float* b_off = (const float*)d_in[2];
    const float* w_mod = (const float*)d_in[3];
    const float* b_mod = (const float*)d_in[4];
    const float* w     = (const float*)d_in[5];
    const float* bias  = (const float*)d_in[6];
    float* out = (float*)d_out;

    transpose_kernel<<<dim3(HW_/32, C_/32, B_), dim3(32, 8)>>>(x);
    wt_kernel<<<(J_*O_ + 255)/256, 256>>>(w);
    conv_kernel<<<dim3(H_, B_), 128>>>(x, w_off, b_off, w_mod, b_mod);
    sample_gemm_kernel<<<dim3(W_/32, H_, B_), 256>>>(bias, out);
}

// round 11
// speedup vs baseline: 2.5973x; 1.1592x over previous
#include <cuda_runtime.h>
#include <cstdint>

// ---------------- problem constants ----------------
#define B_  8
#define C_  64
#define O_  64
#define H_  128
#define W_  128
#define HW_ (H_*W_)          // 16384
#define J_  (C_*9)           // 576
#define ST_ 34               // sv row stride (floats): 2-way STS conflict, LDS.64-clean

// ---------------- scratch (device globals; no allocation allowed) ----------
__device__ __align__(16) float g_xt[B_*HW_*C_];      // NHWC transpose of x
__device__ __align__(16) float g_offm[B_*HW_*27];    // per pixel,k: {dy,dx,mask}
__device__ __align__(16) float g_wt[J_*O_];          // Wt[j][o]

// ---------------- f32x2 helpers ----------------
__device__ __forceinline__ void fma2(unsigned long long &d, unsigned long long a, unsigned long long b) {
    asm("fma.rn.f32x2 %0, %1, %2, %0;" : "+l"(d) : "l"(a), "l"(b));
}
__device__ __forceinline__ unsigned long long pack2(float x, float y) {
    unsigned long long r;
    asm("mov.b64 %0, {%1, %2};" : "=l"(r) : "f"(x), "f"(y));
    return r;
}
__device__ __forceinline__ float2 unpack2(unsigned long long v) {
    float2 r;
    asm("mov.b64 {%0, %1}, %2;" : "=f"(r.x), "=f"(r.y) : "l"(v));
    return r;
}

// ---------------- kernel A: NCHW -> NHWC transpose of x ----------------
__global__ void transpose_kernel(const float* __restrict__ x) {
    __shared__ float tile[32][33];
    int b  = blockIdx.z;
    int s0 = blockIdx.x * 32;
    int c0 = blockIdx.y * 32;
    #pragma unroll
    for (int i = threadIdx.y; i < 32; i += 8)
        tile[i][threadIdx.x] = x[(size_t)(b*C_ + c0 + i) * HW_ + s0 + threadIdx.x];
    __syncthreads();
    #pragma unroll
    for (int i = threadIdx.y; i < 32; i += 8)
        g_xt[(size_t)(b*HW_ + s0 + i) * C_ + c0 + threadIdx.x] = tile[threadIdx.x][i];
}

// ---------------- kernel A2: w (O,C,3,3) -> Wt[j][o] ----------------
__global__ void wt_kernel(const float* __restrict__ w) {
    int idx = blockIdx.x * blockDim.x + threadIdx.x;
    if (idx < J_*O_) {
        int o = idx & 63;
        int j = idx >> 6;
        g_wt[idx] = w[o * J_ + j];
    }
}

// ---------------- kernel B: offset + mask 3x3 conv (27 channels) ----------------
__global__ void conv_kernel(const float* __restrict__ x,
                            const float* __restrict__ w_off,
                            const float* __restrict__ b_off,
                            const float* __restrict__ w_mod,
                            const float* __restrict__ b_mod) {
    __shared__ float ws[32*9*28];
    const int w = threadIdx.x;
    const int h = blockIdx.x;
    const int b = blockIdx.y;

    unsigned long long acc[14];
    #pragma unroll
    for (int j = 0; j < 14; ++j) acc[j] = 0ull;

    for (int half = 0; half < 2; ++half) {
        __syncthreads();
        for (int idx = threadIdx.x; idx < 32*9*28; idx += 128) {
            int j = idx % 28;
            int t = (idx / 28) % 9;
            int c = idx / (28*9) + half*32;
            float v = 0.f;
            if (j < 18)      v = w_off[((j*C_ + c) * 9) + t];
            else if (j < 27) v = w_mod[(((j-18)*C_ + c) * 9) + t];
            ws[idx] = v;
        }
        __syncthreads();

        const float* xb = x + (size_t)(b*C_ + half*32) * HW_;
        for (int c = 0; c < 32; ++c) {
            const float* xc = xb + (size_t)c * HW_;
            #pragma unroll
            for (int t = 0; t < 9; ++t) {
                int yy = h + t/3 - 1;
                int xx = w + t%3 - 1;
                float xv = 0.f;
                if (yy >= 0 && yy < H_ && xx >= 0 && xx < W_)
                    xv = xc[yy*W_ + xx];
                unsigned long long xv2 = pack2(xv, xv);
                const unsigned long long* wp =
                    (const unsigned long long*)&ws[(c*9 + t) * 28];
                #pragma unroll
                for (int j = 0; j < 14; ++j) fma2(acc[j], xv2, wp[j]);
            }
        }
    }

    float ov[28];
    #pragma unroll
    for (int j = 0; j < 14; ++j) {
        float2 f = unpack2(acc[j]);
        ov[2*j] = f.x; ov[2*j+1] = f.y;
    }
    float* om = g_offm + ((size_t)(b*HW_ + h*W_ + w) * 27);
    #pragma unroll
    for (int k = 0; k < 9; ++k) {
        om[k*3 + 0] = ov[2*k]     + b_off[2*k];
        om[k*3 + 1] = ov[2*k + 1] + b_off[2*k + 1];
        float z = ov[18 + k] + b_mod[k];
        om[k*3 + 2] = 2.f / (1.f + expf(-z));
    }
}

// ---------------- kernel C: sampling + per-pixel GEMM (deep register block) --
// 256 threads, 32 pixels (one b,h; 32 consecutive w).
// Phase 0: 288 task records (folded bilinear weights + clamped row offsets).
// Chunk loop (2 x 32 channels):
//   Phase 1: gather -> sv[j_local][pixel]
//   Phase 2: each thread: 4 pixels x 8 outputs, 4-way j-split (72 j / chunk).
// Final: 4-way reduction through smem scratch, add bias, store.
__global__ void __launch_bounds__(256, 3)
sample_gemm_kernel(const float* __restrict__ bias, float* __restrict__ out) {
    __shared__ float sv[288*ST_];    // 39168 B (reused as reduction scratch)
    __shared__ float trw[288*4];     // folded weights
    __shared__ int   trr[288*4];     // clamped NHWC row offsets

    const int tid  = threadIdx.x;
    const int lane = tid & 31;
    const int wid  = tid >> 5;
    const int b  = blockIdx.z;
    const int h  = blockIdx.y;
    const int w0 = blockIdx.x * 32;

    // ---- phase 0: task records ----
    for (int t = tid; t < 288; t += 256) {
        int p = t & 31;
        int k = t >> 5;
        int w = w0 + p;
        const float* om = g_offm + ((size_t)(b*HW_ + h*W_ + w) * 27) + k*3;
        float dy = om[0], dx = om[1], m = om[2];
        float py = dy + (float)(h - 1 + k/3);
        float px = dx + (float)(w - 1 + k%3);
        float y0f = floorf(py), x0f = floorf(px);
        float wy = py - y0f,    wx = px - x0f;
        int y0 = (int)y0f, x0 = (int)x0f;
        int y1 = y0 + 1,   x1 = x0 + 1;
        float fy0 = (y0 >= 0 && y0 < H_) ? 1.f : 0.f;
        float fy1 = (y1 >= 0 && y1 < H_) ? 1.f : 0.f;
        float fx0 = (x0 >= 0 && x0 < W_) ? 1.f : 0.f;
        float fx1 = (x1 >= 0 && x1 < W_) ? 1.f : 0.f;
        int y0c = min(max(y0, 0), H_-1), y1c = min(max(y1, 0), H_-1);
        int x0c = min(max(x0, 0), W_-1), x1c = min(max(x1, 0), W_-1);
        trw[t*4+0] = (1.f-wy)*(1.f-wx) * m * fy0 * fx0;
        trw[t*4+1] = (1.f-wy)*wx       * m * fy0 * fx1;
        trw[t*4+2] = wy*(1.f-wx)       * m * fy1 * fx0;
        trw[t*4+3] = wy*wx             * m * fy1 * fx1;
        trr[t*4+0] = (y0c*W_ + x0c) * C_;
        trr[t*4+1] = (y0c*W_ + x1c) * C_;
        trr[t*4+2] = (y1c*W_ + x0c) * C_;
        trr[t*4+3] = (y1c*W_ + x1c) * C_;
    }

    // phase-2 thread mapping:
    //  pg (0..7): pixels 4pg..4pg+3 ; obase: 8 outputs ; jq (0..3): j-quarter
    const int pg    = lane & 7;
    const int oh    = lane >> 3;                 // 0..3
    const int obase = (wid & 1)*32 + oh*8;
    const int jq    = wid >> 1;                  // 0..3

    unsigned long long acc[4][4];                // [px_local][8 o as 4 f32x2]
    #pragma unroll
    for (int i = 0; i < 4; ++i)
        #pragma unroll
        for (int m = 0; m < 4; ++m) acc[i][m] = 0ull;

    const float* xtb = g_xt + (size_t)b * HW_ * C_;

    for (int ch = 0; ch < 2; ++ch) {
        __syncthreads();
        // ---- phase 1: gather (lane = channel within chunk) ----
        {
            const float* xc = xtb + ch*32 + lane;
            for (int t = wid; t < 288; t += 8) {
                float4 wv = *(const float4*)&trw[t*4];
                int4   rv = *(const int4*)&trr[t*4];
                float v00 = xc[rv.x];
                float v01 = xc[rv.y];
                float v10 = xc[rv.z];
                float v11 = xc[rv.w];
                float s = wv.x*v00 + wv.y*v01 + wv.z*v10 + wv.w*v11;
                int p = t & 31;
                int k = t >> 5;
                sv[(lane*9 + k)*ST_ + p] = s;
            }
        }
        __syncthreads();
        // ---- phase 2: partial GEMM, 72 j's for this (chunk, quarter) ----
        {
            const float* wt  = g_wt + (size_t)(ch*288 + jq*72) * 64 + obase;
            const float* svp = sv + (jq*72)*ST_ + 4*pg;
            #pragma unroll 2
            for (int jj = 0; jj < 72; ++jj) {
                float2 v01 = *(const float2*)(svp + jj*ST_);
                float2 v23 = *(const float2*)(svp + jj*ST_ + 2);
                const ulonglong2* wq = (const ulonglong2*)(wt + (size_t)jj*64);
                ulonglong2 qa = wq[0];
                ulonglong2 qb = wq[1];
                unsigned long long v0 = pack2(v01.x, v01.x);
                unsigned long long v1 = pack2(v01.y, v01.y);
                unsigned long long v2 = pack2(v23.x, v23.x);
                unsigned long long v3 = pack2(v23.y, v23.y);
                fma2(acc[0][0], v0, qa.x); fma2(acc[0][1], v0, qa.y);
                fma2(acc[0][2], v0, qb.x); fma2(acc[0][3], v0, qb.y);
                fma2(acc[1][0], v1, qa.x); fma2(acc[1][1], v1, qa.y);
                fma2(acc[1][2], v1, qb.x); fma2(acc[1][3], v1, qb.y);
                fma2(acc[2][0], v2, qa.x); fma2(acc[2][1], v2, qa.y);
                fma2(acc[2][2], v2, qb.x); fma2(acc[2][3], v2, qb.y);
                fma2(acc[3][0], v3, qa.x); fma2(acc[3][1], v3, qa.y);
                fma2(acc[3][2], v3, qb.x); fma2(acc[3][3], v3, qb.y);
            }
        }
    }

    // ---- reduction across 4 j-quarters (scratch: scr[q-1][p][64]) ----
    __syncthreads();
    float* scr = sv;
    const int p0 = 4*pg;
    if (jq != 0) {
        float* base = scr + (size_t)(jq-1)*2048;
        #pragma unroll
        for (int i = 0; i < 4; ++i) {
            #pragma unroll
            for (int m = 0; m < 4; ++m)
                *(float2*)&base[(p0+i)*64 + obase + 2*m] = unpack2(acc[i][m]);
        }
    }
    __syncthreads();
    if (jq == 0) {
        #pragma unroll
        for (int i = 0; i < 4; ++i) {
            int pp = p0 + i;
            size_t obase_out = (size_t)b*O_*HW_ + (size_t)h*W_ + w0 + pp;
            #pragma unroll
            for (int m = 0; m < 4; ++m) {
                int oo = obase + 2*m;
                float2 a  = unpack2(acc[i][m]);
                float2 s0 = *(float2*)&scr[          (size_t)pp*64 + oo];
                float2 s1 = *(float2*)&scr[2048    + (size_t)pp*64 + oo];
                float2 s2 = *(float2*)&scr[4096    + (size_t)pp*64 + oo];
                float r0 = a.x + s0.x + s1.x + s2.x + bias[oo];
                float r1 = a.y + s0.y + s1.y + s2.y + bias[oo+1];
                out[obase_out + (size_t)oo    *HW_] = r0;
                out[obase_out + (size_t)(oo+1)*HW_] = r1;
            }
        }
    }
}

// ---------------- launch ----------------
extern "C" void kernel_launch(void* const* d_in, const int* in_sizes, int n_in,
                              void* d_out, int out_size) {
    (void)in_sizes; (void)n_in; (void)out_size;
    const float* x     = (const float*)d_in[0];
    const float* w_off = (const float*)d_in[1];
    const float* b_off = (const float*)d_in[2];
    const float* w_mod = (const float*)d_in[3];
    const float* b_mod = (const float*)d_in[4];
    const float* w     = (const float*)d_in[5];
    const float* bias  = (const float*)d_in[6];
    float* out = (float*)d_out;

    transpose_kernel<<<dim3(HW_/32, C_/32, B_), dim3(32, 8)>>>(x);
    wt_kernel<<<(J_*O_ + 255)/256, 256>>>(w);
    conv_kernel<<<dim3(H_, B_), 128>>>(x, w_off, b_off, w_mod, b_mod);
    sample_gemm_kernel<<<dim3(W_/32, H_, B_), 256>>>(bias, out);
}

// round 14
// speedup vs baseline: 2.6056x; 1.0032x over previous
#include <cuda_runtime.h>
#include <cuda_bf16.h>
#include <cstdint>

// ---------------- problem constants ----------------
#define B_  8
#define C_  64
#define O_  64
#define H_  128
#define W_  128
#define HW_ (H_*W_)          // 16384
#define J_  (C_*9)           // 576
#define JP_ (J_*3)           // 1728 bf16-split K
#define KCH_ 432             // j' per chunk (16 channels)
#define AST_ 440             // A smem row stride (bf16)
#define BST_ 72              // B smem row stride (bf16)

#define A_BYTES (128*AST_*2)             // 112640
#define B_OFF   A_BYTES
#define B_BYTES (KCH_*BST_*2)            // 62208
#define SMEM_C  (A_BYTES + B_BYTES)      // 174848

// ---------------- scratch (device globals; no allocation allowed) ----------
__device__ __align__(16) float g_xt[B_*HW_*C_];          // NHWC transpose of x
__device__ __align__(16) float4 g_recw[B_*HW_*9];        // folded bilinear weights
__device__ __align__(16) int4   g_recr[B_*HW_*9];        // clamped NHWC offsets
__device__ __align__(16) unsigned short g_wb[JP_*O_];    // Bt[j'][o] bf16-split

// ---------------- helpers ----------------
__device__ __forceinline__ void fma2(unsigned long long &d, unsigned long long a, unsigned long long b) {
    asm("fma.rn.f32x2 %0, %1, %2, %0;" : "+l"(d) : "l"(a), "l"(b));
}
__device__ __forceinline__ unsigned long long pack2(float x, float y) {
    unsigned long long r;
    asm("mov.b64 %0, {%1, %2};" : "=l"(r) : "f"(x), "f"(y));
    return r;
}
__device__ __forceinline__ float2 unpack2(unsigned long long v) {
    float2 r;
    asm("mov.b64 {%0, %1}, %2;" : "=f"(r.x), "=f"(r.y) : "l"(v));
    return r;
}
__device__ __forceinline__ uint32_t smem_u32(const void* p) {
    uint32_t a;
    asm("{ .reg .u64 t; cvta.to.shared.u64 t, %1; cvt.u32.u64 %0, t; }" : "=r"(a) : "l"(p));
    return a;
}
__device__ __forceinline__ void ldsm_x4(uint32_t &r0, uint32_t &r1, uint32_t &r2, uint32_t &r3, uint32_t a) {
    asm volatile("ldmatrix.sync.aligned.m8n8.x4.shared.b16 {%0,%1,%2,%3}, [%4];"
                 : "=r"(r0), "=r"(r1), "=r"(r2), "=r"(r3) : "r"(a));
}
__device__ __forceinline__ void ldsm_x4_t(uint32_t &r0, uint32_t &r1, uint32_t &r2, uint32_t &r3, uint32_t a) {
    asm volatile("ldmatrix.sync.aligned.m8n8.x4.trans.shared.b16 {%0,%1,%2,%3}, [%4];"
                 : "=r"(r0), "=r"(r1), "=r"(r2), "=r"(r3) : "r"(a));
}
__device__ __forceinline__ void mma16816(float* c, uint32_t a0, uint32_t a1, uint32_t a2, uint32_t a3,
                                         uint32_t b0, uint32_t b1) {
    asm volatile(
        "mma.sync.aligned.m16n8k16.row.col.f32.bf16.bf16.f32 "
        "{%0,%1,%2,%3}, {%4,%5,%6,%7}, {%8,%9}, {%0,%1,%2,%3};"
        : "+f"(c[0]), "+f"(c[1]), "+f"(c[2]), "+f"(c[3])
        : "r"(a0), "r"(a1), "r"(a2), "r"(a3), "r"(b0), "r"(b1));
}

// ---------------- kernel A: NCHW -> NHWC transpose of x ----------------
__global__ void transpose_kernel(const float* __restrict__ x) {
    __shared__ float tile[32][33];
    int b  = blockIdx.z;
    int s0 = blockIdx.x * 32;
    int c0 = blockIdx.y * 32;
    #pragma unroll
    for (int i = threadIdx.y; i < 32; i += 8)
        tile[i][threadIdx.x] = x[(size_t)(b*C_ + c0 + i) * HW_ + s0 + threadIdx.x];
    __syncthreads();
    #pragma unroll
    for (int i = threadIdx.y; i < 32; i += 8)
        g_xt[(size_t)(b*HW_ + s0 + i) * C_ + c0 + threadIdx.x] = tile[threadIdx.x][i];
}

// ---------------- kernel A2: build Bt[j'][o] bf16-split ----------------
// j' = 3*(c*9+t) + u ; u0 = wh, u1 = wl, u2 = wh
__global__ void wb_kernel(const float* __restrict__ w) {
    int idx = blockIdx.x * blockDim.x + threadIdx.x;
    if (idx >= JP_*O_) return;
    int jp = idx >> 6;          // j'
    int o  = idx & 63;
    int jl = jp / 3, u = jp % 3;
    int c = jl / 9, t = jl % 9;
    float v = w[((size_t)o*C_ + c)*9 + t];
    __nv_bfloat16 wh = __float2bfloat16(v);
    __nv_bfloat16 wl = __float2bfloat16(v - __bfloat162float(wh));
    __nv_bfloat16 val = (u == 1) ? wl : wh;
    g_wb[(size_t)jp*O_ + o] = *(unsigned short*)&val;
}

// ---------------- kernel B: offset+mask conv -> sample records --------------
__global__ void conv_kernel(const float* __restrict__ x,
                            const float* __restrict__ w_off,
                            const float* __restrict__ b_off,
                            const float* __restrict__ w_mod,
                            const float* __restrict__ b_mod) {
    __shared__ float ws[32*9*28];
    const int w = threadIdx.x;
    const int h = blockIdx.x;
    const int b = blockIdx.y;

    unsigned long long acc[14];
    #pragma unroll
    for (int j = 0; j < 14; ++j) acc[j] = 0ull;

    for (int half = 0; half < 2; ++half) {
        __syncthreads();
        for (int idx = threadIdx.x; idx < 32*9*28; idx += 128) {
            int j = idx % 28;
            int t = (idx / 28) % 9;
            int c = idx / (28*9) + half*32;
            float v = 0.f;
            if (j < 18)      v = w_off[((j*C_ + c) * 9) + t];
            else if (j < 27) v = w_mod[(((j-18)*C_ + c) * 9) + t];
            ws[idx] = v;
        }
        __syncthreads();

        const float* xb = x + (size_t)(b*C_ + half*32) * HW_;
        for (int c = 0; c < 32; ++c) {
            const float* xc = xb + (size_t)c * HW_;
            #pragma unroll
            for (int t = 0; t < 9; ++t) {
                int yy = h + t/3 - 1;
                int xx = w + t%3 - 1;
                float xv = 0.f;
                if (yy >= 0 && yy < H_ && xx >= 0 && xx < W_)
                    xv = xc[yy*W_ + xx];
                unsigned long long xv2 = pack2(xv, xv);
                const unsigned long long* wp =
                    (const unsigned long long*)&ws[(c*9 + t) * 28];
                #pragma unroll
                for (int j = 0; j < 14; ++j) fma2(acc[j], xv2, wp[j]);
            }
        }
    }

    float ov[28];
    #pragma unroll
    for (int j = 0; j < 14; ++j) {
        float2 f = unpack2(acc[j]);
        ov[2*j] = f.x; ov[2*j+1] = f.y;
    }
    size_t gpx = (size_t)(b*HW_ + h*W_ + w);
    #pragma unroll
    for (int k = 0; k < 9; ++k) {
        float dy = ov[2*k]     + b_off[2*k];
        float dx = ov[2*k + 1] + b_off[2*k + 1];
        float z  = ov[18 + k] + b_mod[k];
        float m  = 2.f / (1.f + expf(-z));
        float py = dy + (float)(h - 1 + k/3);
        float px = dx + (float)(w - 1 + k%3);
        float y0f = floorf(py), x0f = floorf(px);
        float wy = py - y0f,    wx = px - x0f;
        int y0 = (int)y0f, x0 = (int)x0f;
        int y1 = y0 + 1,   x1 = x0 + 1;
        float fy0 = (y0 >= 0 && y0 < H_) ? 1.f : 0.f;
        float fy1 = (y1 >= 0 && y1 < H_) ? 1.f : 0.f;
        float fx0 = (x0 >= 0 && x0 < W_) ? 1.f : 0.f;
        float fx1 = (x1 >= 0 && x1 < W_) ? 1.f : 0.f;
        int y0c = min(max(y0, 0), H_-1), y1c = min(max(y1, 0), H_-1);
        int x0c = min(max(x0, 0), W_-1), x1c = min(max(x1, 0), W_-1);
        g_recw[gpx*9 + k] = make_float4((1.f-wy)*(1.f-wx)*m*fy0*fx0,
                                        (1.f-wy)*wx      *m*fy0*fx1,
                                        wy*(1.f-wx)      *m*fy1*fx0,
                                        wy*wx            *m*fy1*fx1);
        g_recr[gpx*9 + k] = make_int4((y0c*W_ + x0c)*C_, (y0c*W_ + x1c)*C_,
                                      (y1c*W_ + x0c)*C_, (y1c*W_ + x1c)*C_);
    }
}

// ---------------- kernel C: fused sampling + mma.sync bf16-split GEMM -------
// CTA = (b,h): 128 pixels. M=128, N=64, K'=1728 in 4 chunks of 432.
__global__ void __launch_bounds__(256, 1)
sample_mma_kernel(const float* __restrict__ bias, float* __restrict__ out) {
    extern __shared__ __align__(16) char sm[];
    __nv_bfloat16* Ap = (__nv_bfloat16*)sm;
    float* stg = (float*)(sm + B_OFF);          // epilogue stage (reuses B region)

    const uint32_t sbase = smem_u32(sm);
    const uint32_t abase = sbase;
    const uint32_t bbase = sbase + B_OFF;

    const int tid  = threadIdx.x;
    const int lane = tid & 31;
    const int wid  = tid >> 5;
    const int b = blockIdx.y;
    const int h = blockIdx.x;
    const int cl = lane & 15;      // channel within chunk
    const int ph = lane >> 4;      // pixel parity within pair

    float c_[8][4];
    #pragma unroll
    for (int nt = 0; nt < 8; ++nt)
        #pragma unroll
        for (int i = 0; i < 4; ++i) c_[nt][i] = 0.f;

    const float* xtb = g_xt + (size_t)b * HW_ * C_;
    // ldmatrix address components (per-lane constants)
    const uint32_t a_lane = abase + (uint32_t)(wid*16 + (lane & 15))*(AST_*2) + (uint32_t)(lane >> 4)*16;
    const uint32_t b_row  = (uint32_t)((lane & 7) + ((lane >> 3) & 1)*8);
    const uint32_t b_lane = bbase + b_row*(BST_*2) + (uint32_t)(lane >> 4)*16;

    for (int cc = 0; cc < 4; ++cc) {
        __syncthreads();   // previous mma phase done before overwriting A/B
        // ---- load B chunk: [432][64] gmem rows -> [432][72] smem rows ----
        {
            const char* src = (const char*)(g_wb + (size_t)cc*KCH_*O_);
            for (int i = tid; i < KCH_*8; i += 256) {
                int row = i >> 3, seg = i & 7;
                *(float4*)(sm + B_OFF + row*(BST_*2) + seg*16) =
                    *(const float4*)(src + (row*O_ + seg*8)*2);
            }
        }
        // ---- sampling: 64 px-pairs x 16 channels -> A' bf16 hi/lo ----
        {
            const float* xc = xtb + cc*16 + cl;
            for (int t8 = 0; t8 < 8; ++t8) {
                int px = (t8*8 + wid)*2 + ph;
                size_t rb = ((size_t)(b*HW_ + h*W_ + px))*9;
                #pragma unroll
                for (int k = 0; k < 9; ++k) {
                    float4 wv = g_recw[rb + k];
                    int4   rv = g_recr[rb + k];
                    float s = wv.x*__ldg(xc + rv.x) + wv.y*__ldg(xc + rv.y)
                            + wv.z*__ldg(xc + rv.z) + wv.w*__ldg(xc + rv.w);
                    __nv_bfloat16 vh = __float2bfloat16(s);
                    __nv_bfloat16 vl = __float2bfloat16(s - __bfloat162float(vh));
                    __nv_bfloat16* ar = Ap + px*AST_ + (cl*9 + k)*3;
                    ar[0] = vh; ar[1] = vh; ar[2] = vl;
                }
            }
        }
        __syncthreads();
        // ---- mma: warp = m16 tile (rows 16*wid..), 8 n-tiles, 27 k-steps ----
        #pragma unroll 1
        for (int s = 0; s < 27; ++s) {
            uint32_t a0, a1, a2, a3;
            ldsm_x4(a0, a1, a2, a3, a_lane + (uint32_t)s*32);
            uint32_t brow = b_lane + (uint32_t)s*16*(BST_*2);
            #pragma unroll
            for (int np = 0; np < 4; ++np) {
                uint32_t b0, b1, b2, b3;
                ldsm_x4_t(b0, b1, b2, b3, brow + (uint32_t)np*32);
                mma16816(c_[2*np    ], a0, a1, a2, a3, b0, b1);
                mma16816(c_[2*np + 1], a0, a1, a2, a3, b2, b3);
            }
        }
    }

    // ---- epilogue: stage to [o][px] fp32 in smem, then coalesced out ----
    __syncthreads();
    {
        int pxl = wid*16 + (lane >> 2);
        int oc  = (lane & 3)*2;
        #pragma unroll
        for (int nt = 0; nt < 8; ++nt) {
            int o = nt*8 + oc;
            stg[(o    )*128 + pxl    ] = c_[nt][0];
            stg[(o + 1)*128 + pxl    ] = c_[nt][1];
            stg[(o    )*128 + pxl + 8] = c_[nt][2];
            stg[(o + 1)*128 + pxl + 8] = c_[nt][3];
        }
    }
    __syncthreads();
    #pragma unroll
    for (int o8 = 0; o8 < 8; ++o8) {
        int o = wid*8 + o8;
        float bv = bias[o];
        size_t ob = ((size_t)(b*O_ + o))*HW_ + (size_t)h*W_;
        #pragma unroll
        for (int q = 0; q < 4; ++q)
            out[ob + q*32 + lane] = stg[o*128 + q*32 + lane] + bv;
    }
}

// ---------------- launch ----------------
extern "C" void kernel_launch(void* const* d_in, const int* in_sizes, int n_in,
                              void* d_out, int out_size) {
    (void)in_sizes; (void)n_in; (void)out_size;
    const float* x     = (const float*)d_in[0];
    const float* w_off = (const float*)d_in[1];
    const float* b_off = (const float*)d_in[2];
    const float* w_mod = (const float*)d_in[3];
    const float* b_mod = (const float*)d_in[4];
    const float* w     = (const float*)d_in[5];
    const float* bias  = (const float*)d_in[6];
    float* out = (float*)d_out;

    cudaFuncSetAttribute(sample_mma_kernel,
                         cudaFuncAttributeMaxDynamicSharedMemorySize, SMEM_C);

    transpose_kernel<<<dim3(HW_/32, C_/32, B_), dim3(32, 8)>>>(x);
    wb_kernel<<<(JP_*O_ + 255)/256, 256>>>(w);
    conv_kernel<<<dim3(H_, B_), 128>>>(x, w_off, b_off, w_mod, b_mod);
    sample_mma_kernel<<<dim3(H_, B_), 256, SMEM_C>>>(bias, out);
}